// round 11
// baseline (speedup 1.0000x reference)
#include <cuda_runtime.h>
#include <cuda_fp16.h>
#include <math.h>
#include <stdint.h>

#define BB 4
#define SS 2048
#define DD 1024
#define HH 16
#define DKK 64
#define NTOT (BB*SS*DD)

// ---------------------------------------------------------------------------
// Scratch (device globals — no allocations allowed)
// ---------------------------------------------------------------------------
__device__ float  g_cs[SS * 32];
__device__ float  g_sn[SS * 32];
__device__ __half g_xh[NTOT];
__device__ __half g_wh[4 * DD * DD];
__device__ __half g_qh[NTOT];
__device__ __half g_kh[NTOT];
__device__ __half g_vh[NTOT];
__device__ __half g_oh[NTOT];

// ---------------------------------------------------------------------------
// mma / ldmatrix / cp.async helpers
// ---------------------------------------------------------------------------
__device__ __forceinline__ void mma_f16(float* c, const unsigned* a, const unsigned* b) {
    asm volatile(
        "mma.sync.aligned.m16n8k16.row.col.f32.f16.f16.f32 "
        "{%0,%1,%2,%3},{%4,%5,%6,%7},{%8,%9},{%0,%1,%2,%3};\n"
        : "+f"(c[0]), "+f"(c[1]), "+f"(c[2]), "+f"(c[3])
        : "r"(a[0]), "r"(a[1]), "r"(a[2]), "r"(a[3]), "r"(b[0]), "r"(b[1]));
}
__device__ __forceinline__ void ldsm4(unsigned* r, uint32_t addr) {
    asm volatile("ldmatrix.sync.aligned.m8n8.x4.shared.b16 {%0,%1,%2,%3}, [%4];"
        : "=r"(r[0]), "=r"(r[1]), "=r"(r[2]), "=r"(r[3]) : "r"(addr));
}
__device__ __forceinline__ void ldsm4t(unsigned* r, uint32_t addr) {
    asm volatile("ldmatrix.sync.aligned.m8n8.x4.trans.shared.b16 {%0,%1,%2,%3}, [%4];"
        : "=r"(r[0]), "=r"(r[1]), "=r"(r[2]), "=r"(r[3]) : "r"(addr));
}
__device__ __forceinline__ void cp16(uint32_t dst, const void* src) {
    asm volatile("cp.async.cg.shared.global [%0], [%1], 16;" :: "r"(dst), "l"(src));
}
__device__ __forceinline__ uint32_t smem_u32(const void* p) {
    uint32_t a;
    asm("{ .reg .u64 t; cvta.to.shared.u64 t, %1; cvt.u32.u64 %0, t; }" : "=r"(a) : "l"(p));
    return a;
}
__device__ __forceinline__ unsigned packh2(float a, float b) {
    __half2 h = __floats2half2_rn(a, b);
    return *(unsigned*)&h;
}
__device__ __forceinline__ unsigned ex2h2(unsigned x) {
    unsigned y;
    asm("ex2.approx.f16x2 %0, %1;" : "=r"(y) : "r"(x));
    return y;
}

// ---------------------------------------------------------------------------
// RoPE table (fp64-exact inv_freq)
// ---------------------------------------------------------------------------
__global__ void rope_table(const int* __restrict__ tp) {
    int i = blockIdx.x * blockDim.x + threadIdx.x;
    int s = i >> 5, p = i & 31;
    float pos = (float)tp[s];
    float inv = (float)exp(-(double)p * 0.28782313662425572);
    float ang = pos * inv;
    float sn, cs;
    sincosf(ang, &sn, &cs);
    g_cs[i] = cs;
    g_sn[i] = sn;
}

// ---------------------------------------------------------------------------
// One-shot fp32 -> fp16 conversion: x + 4 weights
// ---------------------------------------------------------------------------
#define NX4 (NTOT/4)
#define NW4 ((DD*DD)/4)
__global__ void conv_all(const float* __restrict__ x,  const float* __restrict__ wq,
                         const float* __restrict__ wk, const float* __restrict__ wv,
                         const float* __restrict__ wo) {
    int i = blockIdx.x * blockDim.x + threadIdx.x;
    const float* src;
    __half* dst;
    int j;
    if (i < NX4) { src = x; dst = g_xh; j = i; }
    else {
        int r = i - NX4;
        int seg = r / NW4;
        j = r - seg * NW4;
        src = (seg == 0) ? wq : (seg == 1) ? wk : (seg == 2) ? wv : wo;
        dst = g_wh + (size_t)seg * DD * DD;
    }
    float4 v = ((const float4*)src)[j];
    ((__half2*)dst)[2 * j]     = __floats2half2_rn(v.x, v.y);
    ((__half2*)dst)[2 * j + 1] = __floats2half2_rn(v.z, v.w);
}

// ---------------------------------------------------------------------------
// GEMM mainloop: single barrier per k-stage.
// ---------------------------------------------------------------------------
#define GSTG 20480
__device__ __forceinline__ void gemm_main(uint32_t smb, const __half* Ag,
                                          const __half* Bg, float acc[4][4][4]) {
    const int t = threadIdx.x;
    const int lane = t & 31, warp = t >> 5;
    const int wm = (warp >> 2) * 64, wn = (warp & 3) * 32;
    const int chunk = t & 3, row0 = t >> 2;
    Ag += chunk * 8;
    Bg += chunk * 8;

    const uint32_t a_off = ((wm + (lane & 15)) * 40 + (lane >> 4) * 8) * 2;
    const int br = lane & 7, bg = lane >> 3;
    const uint32_t b_off = ((wn + br + (bg >> 1) * 8) * 40 + (bg & 1) * 8) * 2;

#pragma unroll
    for (int ps = 0; ps < 3; ps++) {
        uint32_t sb = smb + ps * GSTG;
        const __half* ga = Ag + ps * 32;
        const __half* gb = Bg + ps * 32;
#pragma unroll
        for (int j = 0; j < 2; j++) {
            int row = row0 + j * 64;
            cp16(sb + row * 80 + chunk * 16, ga + (size_t)row * DD);
            cp16(sb + 128 * 80 + row * 80 + chunk * 16, gb + (size_t)row * DD);
        }
        asm volatile("cp.async.commit_group;");
    }

    for (int s = 0; s < 32; s++) {
        asm volatile("cp.async.wait_group 2;");
        __syncthreads();
        const uint32_t sA = smb + (s & 3) * GSTG;
        const uint32_t sB = sA + 128 * 80;
#pragma unroll
        for (int ks = 0; ks < 2; ks++) {
            unsigned af[4][4], bf[2][4];
#pragma unroll
            for (int mt = 0; mt < 4; mt++)
                ldsm4(af[mt], sA + a_off + mt * (16 * 80) + ks * 32);
#pragma unroll
            for (int np = 0; np < 2; np++)
                ldsm4(bf[np], sB + b_off + np * (16 * 80) + ks * 32);
#pragma unroll
            for (int mt = 0; mt < 4; mt++)
#pragma unroll
                for (int nt = 0; nt < 4; nt++)
                    mma_f16(acc[mt][nt], af[mt], &bf[nt >> 1][(nt & 1) * 2]);
        }
        if (s + 3 < 32) {
            uint32_t sb = smb + ((s + 3) & 3) * GSTG;
            const __half* ga = Ag + (s + 3) * 32;
            const __half* gb = Bg + (s + 3) * 32;
#pragma unroll
            for (int j = 0; j < 2; j++) {
                int row = row0 + j * 64;
                cp16(sb + row * 80 + chunk * 16, ga + (size_t)row * DD);
                cp16(sb + 128 * 80 + row * 80 + chunk * 16, gb + (size_t)row * DD);
            }
        }
        asm volatile("cp.async.commit_group;");
    }
}

// ---------------------------------------------------------------------------
// Fused QKV GEMM + RoPE epilogue. Q scale 0.125*log2(e) (exp2 softmax).
// ---------------------------------------------------------------------------
#define QSCALE 0.1803368801111204f   // 0.125 * log2(e)
__global__ __launch_bounds__(256) void gemm_qkv() {
    extern __shared__ __align__(128) char smem[];
    const uint32_t smb = smem_u32(smem);
    const int t = threadIdx.x;
    const int lane = t & 31, warp = t >> 5;
    const int qr = lane >> 2, ql = lane & 3;
    const int wm = (warp >> 2) * 64, wn = (warp & 3) * 32;
    const int w  = blockIdx.x >> 3;
    const int bn = (blockIdx.x & 7) * 128;
    const int bm = blockIdx.y * 128;

    float acc[4][4][4] = {};
    gemm_main(smb, g_xh + (size_t)bm * DD, g_wh + (size_t)w * DD * DD + (size_t)bn * DD, acc);

    const int r0 = bm + wm + qr;
    const int c0 = bn + wn + 2 * ql;
    if (w == 2) {
#pragma unroll
        for (int mt = 0; mt < 4; mt++)
#pragma unroll
            for (int nt = 0; nt < 4; nt++) {
                __half* vp = g_vh + (size_t)(r0 + mt * 16) * DD + c0 + nt * 8;
                *(__half2*)vp = __floats2half2_rn(acc[mt][nt][0], acc[mt][nt][1]);
                *(__half2*)(vp + 8 * DD) = __floats2half2_rn(acc[mt][nt][2], acc[mt][nt][3]);
            }
    } else {
        __half* dst = (w == 0) ? g_qh : g_kh;
        const float sc = (w == 0) ? QSCALE : 1.0f;
#pragma unroll
        for (int mt = 0; mt < 4; mt++) {
            int rA = r0 + mt * 16;
            int rB = rA + 8;
            int sA = rA & (SS - 1), sB = rB & (SS - 1);
#pragma unroll
            for (int nt = 0; nt < 4; nt++) {
                int cc = c0 + nt * 8;
                int p = (cc & 63) >> 1;
                float csA = g_cs[sA * 32 + p], snA = g_sn[sA * 32 + p];
                float csB = g_cs[sB * 32 + p], snB = g_sn[sB * 32 + p];
                float a0 = acc[mt][nt][0], a1 = acc[mt][nt][1];
                float b0 = acc[mt][nt][2], b1 = acc[mt][nt][3];
                __half* dp = dst + (size_t)rA * DD + cc;
                *(__half2*)dp = __floats2half2_rn((a0 * csA - a1 * snA) * sc,
                                                  (a0 * snA + a1 * csA) * sc);
                *(__half2*)(dp + 8 * DD) = __floats2half2_rn((b0 * csB - b1 * snB) * sc,
                                                             (b0 * snB + b1 * csB) * sc);
            }
        }
    }
}

// ---------------------------------------------------------------------------
// Output projection GEMM
// ---------------------------------------------------------------------------
__global__ __launch_bounds__(256) void gemm_out(float* __restrict__ C) {
    extern __shared__ __align__(128) char smem[];
    const uint32_t smb = smem_u32(smem);
    const int t = threadIdx.x;
    const int lane = t & 31, warp = t >> 5;
    const int qr = lane >> 2, ql = lane & 3;
    const int wm = (warp >> 2) * 64, wn = (warp & 3) * 32;
    const int bn = blockIdx.x * 128;
    const int bm = blockIdx.y * 128;

    float acc[4][4][4] = {};
    gemm_main(smb, g_oh + (size_t)bm * DD, g_wh + (size_t)3 * DD * DD + (size_t)bn * DD, acc);

    const int r0 = bm + wm + qr;
    const int c0 = bn + wn + 2 * ql;
#pragma unroll
    for (int mt = 0; mt < 4; mt++)
#pragma unroll
        for (int nt = 0; nt < 4; nt++) {
            float* cp = C + (size_t)(r0 + mt * 16) * DD + c0 + nt * 8;
            *(float2*)cp = make_float2(acc[mt][nt][0], acc[mt][nt][1]);
            *(float2*)(cp + 8 * DD) = make_float2(acc[mt][nt][2], acc[mt][nt][3]);
        }
}

// ---------------------------------------------------------------------------
// fp16 flash attention v5: no-max softmax, f16x2 ex2, row-sums via ones-column
// mma (V pad col 64 = 1.0), masked-warp skip on 2nd diagonal tile.
// q-tile 128 (8 warps), k-tile 64, 3-stage cp.async ring, 1 barrier/k-tile.
// ---------------------------------------------------------------------------
#define HPAD 72
#define QT_B  (0)
#define KT_B(s) (128 * HPAD * 2 + (s) * (2 * 64 * HPAD * 2))
#define VT_B(s) (KT_B(s) + 64 * HPAD * 2)
#define ATTN_SMEM_B (128 * HPAD * 2 + 6 * 64 * HPAD * 2 + 256)   // +256 ldsm OOB pad

__global__ __launch_bounds__(256) void attn_h() {
    extern __shared__ __align__(16) __half smh[];
    const uint32_t u0 = smem_u32(smh);
    __half* Qs = smh;

    const int h = blockIdx.y, b = blockIdx.z;
    const int t = threadIdx.x;
    const int lane = t & 31, warp = t >> 5;
    const int qr = lane >> 2, ql = lane & 3;
    const int br = lane & 7, bg = lane >> 3;

    const uint32_t offA  = ((warp * 16 + (lane & 15)) * HPAD + (lane >> 4) * 8) * 2;
    const uint32_t offBk = ((br + (bg >> 1) * 8) * HPAD + (bg & 1) * 8) * 2;
    const uint32_t offBv = ((br + (bg & 1) * 8) * HPAD + (bg >> 1) * 8) * 2;

    // ones-column init: V pad col 64 = 1.0 in all 3 ring buffers (cp.async
    // only ever writes cols 0..63, so this survives the whole kernel)
    if (t < 64) {
#pragma unroll
        for (int s = 0; s < 3; s++)
            smh[VT_B(s) / 2 + t * HPAD + 64] = __float2half(1.0f);
    }

#define AKLOAD(kt_, buf_) do {                                                      \
        const __half* kb_ = g_kh + ((size_t)b * SS + (size_t)(kt_) * 64) * DD + h * DKK; \
        const __half* vb_ = g_vh + ((size_t)b * SS + (size_t)(kt_) * 64) * DD + h * DKK; \
        uint32_t kd_ = u0 + KT_B(buf_), vd_ = u0 + VT_B(buf_);                      \
        _Pragma("unroll")                                                           \
        for (int i_ = 0; i_ < 2; i_++) {                                            \
            int idx_ = t + i_ * 256;                                                \
            int r_ = idx_ >> 3, cb_ = (idx_ & 7) * 16;                              \
            cp16(kd_ + r_ * (HPAD * 2) + cb_, kb_ + (size_t)r_ * DD + (idx_ & 7) * 8); \
            cp16(vd_ + r_ * (HPAD * 2) + cb_, vb_ + (size_t)r_ * DD + (idx_ & 7) * 8); \
        }                                                                           \
    } while (0)

#pragma unroll
    for (int pass = 0; pass < 2; pass++) {
        const int qt = pass ? blockIdx.x : 15 - blockIdx.x;   // q-tile of 128 rows
        const int nk = 2 * qt + 2;

        // load Q tile: 128 rows x 64 halves
        const __half* qb = g_qh + ((size_t)b * SS + (size_t)qt * 128) * DD + h * DKK;
#pragma unroll
        for (int i = 0; i < 4; i++) {
            int idx = t + i * 256;
            int r = idx >> 3, c = (idx & 7) * 8;
            *(uint4*)&Qs[r * HPAD + c] = *(const uint4*)&qb[(size_t)r * DD + c];
        }

        float o[8][4] = {};
        float ol[4] = {};          // ones-column accumulator (row sums of P)

        AKLOAD(0, 0);
        asm volatile("cp.async.commit_group;");
        AKLOAD(1, 1);
        asm volatile("cp.async.commit_group;");

        int buf = 0;
        for (int kt = 0; kt < nk; kt++) {
            asm volatile("cp.async.wait_group 1;");
            __syncthreads();

            const uint32_t u_k = u0 + KT_B(buf);
            const uint32_t u_v = u0 + VT_B(buf);
            buf = (buf == 2) ? 0 : buf + 1;

            // warps 0-3 are fully masked on the 2nd diagonal tile -> skip work
            const bool active = !(kt == 2 * qt + 1 && warp < 4);
            if (active) {
                // ---- S = Q K^T (log2-scaled) ----
                float sv[8][4] = {};
#pragma unroll
                for (int ks = 0; ks < 4; ks++) {
                    unsigned a[4];
                    ldsm4(a, u0 + QT_B + offA + ks * 32);
#pragma unroll
                    for (int np = 0; np < 4; np++) {
                        unsigned bf[4];
                        ldsm4(bf, u_k + offBk + np * (16 * HPAD * 2) + ks * 32);
                        mma_f16(sv[2 * np],     a, &bf[0]);
                        mma_f16(sv[2 * np + 1], a, &bf[2]);
                    }
                }

                // ---- causal mask ----
                if (kt >= 2 * qt) {
                    const int off = (kt - 2 * qt) * 64;
                    const int r_lo = warp * 16 + qr - off, r_hi = r_lo + 8;
#pragma unroll
                    for (int nt = 0; nt < 8; nt++) {
                        int c0 = nt * 8 + 2 * ql, c1 = c0 + 1;
                        if (c0 > r_lo) sv[nt][0] = -1e30f;
                        if (c1 > r_lo) sv[nt][1] = -1e30f;
                        if (c0 > r_hi) sv[nt][2] = -1e30f;
                        if (c1 > r_hi) sv[nt][3] = -1e30f;
                    }
                }

                // ---- P = exp2(s) in f16x2 (pack, then vector ex2) ----
                unsigned pa[4][4];
#pragma unroll
                for (int ks = 0; ks < 4; ks++) {
                    pa[ks][0] = ex2h2(packh2(sv[2 * ks][0],     sv[2 * ks][1]));
                    pa[ks][1] = ex2h2(packh2(sv[2 * ks][2],     sv[2 * ks][3]));
                    pa[ks][2] = ex2h2(packh2(sv[2 * ks + 1][0], sv[2 * ks + 1][1]));
                    pa[ks][3] = ex2h2(packh2(sv[2 * ks + 1][2], sv[2 * ks + 1][3]));
                }

                // ---- O += P V ; row sums via ones-column (np==4) ----
#pragma unroll
                for (int ks = 0; ks < 4; ks++) {
#pragma unroll
                    for (int np = 0; np < 5; np++) {
                        unsigned bf[4];
                        ldsm4t(bf, u_v + offBv + ks * (16 * HPAD * 2) + np * 32);
                        if (np < 4) {
                            mma_f16(o[2 * np],     pa[ks], &bf[0]);
                            mma_f16(o[2 * np + 1], pa[ks], &bf[2]);
                        } else {
                            mma_f16(ol, pa[ks], &bf[0]);   // col 64 = ones
                        }
                    }
                }
            }

            if (kt + 2 < nk) AKLOAD(kt + 2, (kt + 2) % 3);
            asm volatile("cp.async.commit_group;");
        }

        // ---- row sums live in ol[0]/ol[2] on ql==0 lanes; broadcast ----
        float l0 = __shfl_sync(0xffffffffu, ol[0], lane & 28);
        float l1 = __shfl_sync(0xffffffffu, ol[2], lane & 28);

        const float inv0 = 1.0f / l0, inv1 = 1.0f / l1;
        __half* ob = g_oh + ((size_t)b * SS + (size_t)qt * 128 + warp * 16 + qr) * DD + h * DKK;
#pragma unroll
        for (int nt = 0; nt < 8; nt++) {
            int c0 = nt * 8 + 2 * ql;
            *(__half2*)&ob[c0] = __floats2half2_rn(o[nt][0] * inv0, o[nt][1] * inv0);
            *(__half2*)&ob[(size_t)8 * DD + c0] = __floats2half2_rn(o[nt][2] * inv1, o[nt][3] * inv1);
        }
        __syncthreads();
    }
#undef AKLOAD
}

// ---------------------------------------------------------------------------
extern "C" void kernel_launch(void* const* d_in, const int* in_sizes, int n_in,
                              void* d_out, int out_size) {
    const float* x  = (const float*)d_in[0];
    const float* wq = (const float*)d_in[1];
    const float* wk = (const float*)d_in[2];
    const float* wv = (const float*)d_in[3];
    const float* wo = (const float*)d_in[4];
    const int*   tp = (const int*)d_in[5];
    float* out = (float*)d_out;

    rope_table<<<(SS * 32) / 256, 256>>>(tp);
    conv_all<<<(NX4 + 4 * NW4) / 256, 256>>>(x, wq, wk, wv, wo);

    const int GEMM_SMEM = 4 * GSTG;          // 81920 B
    cudaFuncSetAttribute(gemm_qkv, cudaFuncAttributeMaxDynamicSharedMemorySize, GEMM_SMEM);
    cudaFuncSetAttribute(gemm_out, cudaFuncAttributeMaxDynamicSharedMemorySize, GEMM_SMEM);

    gemm_qkv<<<dim3(24, (BB * SS) / 128), 256, GEMM_SMEM>>>();

    cudaFuncSetAttribute(attn_h, cudaFuncAttributeMaxDynamicSharedMemorySize, ATTN_SMEM_B);
    attn_h<<<dim3(SS / 256, HH, BB), 256, ATTN_SMEM_B>>>();

    gemm_out<<<dim3(DD / 128, (BB * SS) / 128), 256, GEMM_SMEM>>>(out);
}

// round 12
// speedup vs baseline: 1.4129x; 1.4129x over previous
#include <cuda_runtime.h>
#include <cuda_fp16.h>
#include <math.h>
#include <stdint.h>

#define BB 4
#define SS 2048
#define DD 1024
#define HH 16
#define DKK 64
#define NTOT (BB*SS*DD)

// ---------------------------------------------------------------------------
// Scratch (device globals — no allocations allowed)
// ---------------------------------------------------------------------------
__device__ float  g_cs[SS * 32];
__device__ float  g_sn[SS * 32];
__device__ __half g_xh[NTOT];
__device__ __half g_wh[4 * DD * DD];
__device__ __half g_qh[NTOT];
__device__ __half g_kh[NTOT];
__device__ __half g_vh[NTOT];
__device__ __half g_oh[NTOT];

// ---------------------------------------------------------------------------
// mma / ldmatrix / cp.async helpers
// ---------------------------------------------------------------------------
__device__ __forceinline__ void mma_f16(float* c, const unsigned* a, const unsigned* b) {
    asm volatile(
        "mma.sync.aligned.m16n8k16.row.col.f32.f16.f16.f32 "
        "{%0,%1,%2,%3},{%4,%5,%6,%7},{%8,%9},{%0,%1,%2,%3};\n"
        : "+f"(c[0]), "+f"(c[1]), "+f"(c[2]), "+f"(c[3])
        : "r"(a[0]), "r"(a[1]), "r"(a[2]), "r"(a[3]), "r"(b[0]), "r"(b[1]));
}
__device__ __forceinline__ void ldsm4(unsigned* r, uint32_t addr) {
    asm volatile("ldmatrix.sync.aligned.m8n8.x4.shared.b16 {%0,%1,%2,%3}, [%4];"
        : "=r"(r[0]), "=r"(r[1]), "=r"(r[2]), "=r"(r[3]) : "r"(addr));
}
__device__ __forceinline__ void ldsm4t(unsigned* r, uint32_t addr) {
    asm volatile("ldmatrix.sync.aligned.m8n8.x4.trans.shared.b16 {%0,%1,%2,%3}, [%4];"
        : "=r"(r[0]), "=r"(r[1]), "=r"(r[2]), "=r"(r[3]) : "r"(addr));
}
__device__ __forceinline__ void cp16(uint32_t dst, const void* src) {
    asm volatile("cp.async.cg.shared.global [%0], [%1], 16;" :: "r"(dst), "l"(src));
}
__device__ __forceinline__ uint32_t smem_u32(const void* p) {
    uint32_t a;
    asm("{ .reg .u64 t; cvta.to.shared.u64 t, %1; cvt.u32.u64 %0, t; }" : "=r"(a) : "l"(p));
    return a;
}
__device__ __forceinline__ unsigned packh2(float a, float b) {
    __half2 h = __floats2half2_rn(a, b);
    return *(unsigned*)&h;
}
__device__ __forceinline__ float ex2(float x) {
    float y;
    asm("ex2.approx.f32 %0, %1;" : "=f"(y) : "f"(x));
    return y;
}

// ---------------------------------------------------------------------------
// RoPE table (fp64-exact inv_freq)
// ---------------------------------------------------------------------------
__global__ void rope_table(const int* __restrict__ tp) {
    int i = blockIdx.x * blockDim.x + threadIdx.x;
    int s = i >> 5, p = i & 31;
    float pos = (float)tp[s];
    float inv = (float)exp(-(double)p * 0.28782313662425572);
    float ang = pos * inv;
    float sn, cs;
    sincosf(ang, &sn, &cs);
    g_cs[i] = cs;
    g_sn[i] = sn;
}

// ---------------------------------------------------------------------------
// One-shot fp32 -> fp16 conversion: x + 4 weights
// ---------------------------------------------------------------------------
#define NX4 (NTOT/4)
#define NW4 ((DD*DD)/4)
__global__ void conv_all(const float* __restrict__ x,  const float* __restrict__ wq,
                         const float* __restrict__ wk, const float* __restrict__ wv,
                         const float* __restrict__ wo) {
    int i = blockIdx.x * blockDim.x + threadIdx.x;
    const float* src;
    __half* dst;
    int j;
    if (i < NX4) { src = x; dst = g_xh; j = i; }
    else {
        int r = i - NX4;
        int seg = r / NW4;
        j = r - seg * NW4;
        src = (seg == 0) ? wq : (seg == 1) ? wk : (seg == 2) ? wv : wo;
        dst = g_wh + (size_t)seg * DD * DD;
    }
    float4 v = ((const float4*)src)[j];
    ((__half2*)dst)[2 * j]     = __floats2half2_rn(v.x, v.y);
    ((__half2*)dst)[2 * j + 1] = __floats2half2_rn(v.z, v.w);
}

// ---------------------------------------------------------------------------
// GEMM mainloop: single barrier per k-stage.
// ---------------------------------------------------------------------------
#define GSTG 20480
__device__ __forceinline__ void gemm_main(uint32_t smb, const __half* Ag,
                                          const __half* Bg, float acc[4][4][4]) {
    const int t = threadIdx.x;
    const int lane = t & 31, warp = t >> 5;
    const int wm = (warp >> 2) * 64, wn = (warp & 3) * 32;
    const int chunk = t & 3, row0 = t >> 2;
    Ag += chunk * 8;
    Bg += chunk * 8;

    const uint32_t a_off = ((wm + (lane & 15)) * 40 + (lane >> 4) * 8) * 2;
    const int br = lane & 7, bg = lane >> 3;
    const uint32_t b_off = ((wn + br + (bg >> 1) * 8) * 40 + (bg & 1) * 8) * 2;

#pragma unroll
    for (int ps = 0; ps < 3; ps++) {
        uint32_t sb = smb + ps * GSTG;
        const __half* ga = Ag + ps * 32;
        const __half* gb = Bg + ps * 32;
#pragma unroll
        for (int j = 0; j < 2; j++) {
            int row = row0 + j * 64;
            cp16(sb + row * 80 + chunk * 16, ga + (size_t)row * DD);
            cp16(sb + 128 * 80 + row * 80 + chunk * 16, gb + (size_t)row * DD);
        }
        asm volatile("cp.async.commit_group;");
    }

    for (int s = 0; s < 32; s++) {
        asm volatile("cp.async.wait_group 2;");
        __syncthreads();
        const uint32_t sA = smb + (s & 3) * GSTG;
        const uint32_t sB = sA + 128 * 80;
#pragma unroll
        for (int ks = 0; ks < 2; ks++) {
            unsigned af[4][4], bf[2][4];
#pragma unroll
            for (int mt = 0; mt < 4; mt++)
                ldsm4(af[mt], sA + a_off + mt * (16 * 80) + ks * 32);
#pragma unroll
            for (int np = 0; np < 2; np++)
                ldsm4(bf[np], sB + b_off + np * (16 * 80) + ks * 32);
#pragma unroll
            for (int mt = 0; mt < 4; mt++)
#pragma unroll
                for (int nt = 0; nt < 4; nt++)
                    mma_f16(acc[mt][nt], af[mt], &bf[nt >> 1][(nt & 1) * 2]);
        }
        if (s + 3 < 32) {
            uint32_t sb = smb + ((s + 3) & 3) * GSTG;
            const __half* ga = Ag + (s + 3) * 32;
            const __half* gb = Bg + (s + 3) * 32;
#pragma unroll
            for (int j = 0; j < 2; j++) {
                int row = row0 + j * 64;
                cp16(sb + row * 80 + chunk * 16, ga + (size_t)row * DD);
                cp16(sb + 128 * 80 + row * 80 + chunk * 16, gb + (size_t)row * DD);
            }
        }
        asm volatile("cp.async.commit_group;");
    }
}

// ---------------------------------------------------------------------------
// Fused QKV GEMM + RoPE epilogue. Q scale 0.125*log2(e) (exp2 softmax).
// ---------------------------------------------------------------------------
#define QSCALE 0.1803368801111204f   // 0.125 * log2(e)
__global__ __launch_bounds__(256) void gemm_qkv() {
    extern __shared__ __align__(128) char smem[];
    const uint32_t smb = smem_u32(smem);
    const int t = threadIdx.x;
    const int lane = t & 31, warp = t >> 5;
    const int qr = lane >> 2, ql = lane & 3;
    const int wm = (warp >> 2) * 64, wn = (warp & 3) * 32;
    const int w  = blockIdx.x >> 3;
    const int bn = (blockIdx.x & 7) * 128;
    const int bm = blockIdx.y * 128;

    float acc[4][4][4] = {};
    gemm_main(smb, g_xh + (size_t)bm * DD, g_wh + (size_t)w * DD * DD + (size_t)bn * DD, acc);

    const int r0 = bm + wm + qr;
    const int c0 = bn + wn + 2 * ql;
    if (w == 2) {
#pragma unroll
        for (int mt = 0; mt < 4; mt++)
#pragma unroll
            for (int nt = 0; nt < 4; nt++) {
                __half* vp = g_vh + (size_t)(r0 + mt * 16) * DD + c0 + nt * 8;
                *(__half2*)vp = __floats2half2_rn(acc[mt][nt][0], acc[mt][nt][1]);
                *(__half2*)(vp + 8 * DD) = __floats2half2_rn(acc[mt][nt][2], acc[mt][nt][3]);
            }
    } else {
        __half* dst = (w == 0) ? g_qh : g_kh;
        const float sc = (w == 0) ? QSCALE : 1.0f;
#pragma unroll
        for (int mt = 0; mt < 4; mt++) {
            int rA = r0 + mt * 16;
            int rB = rA + 8;
            int sA = rA & (SS - 1), sB = rB & (SS - 1);
#pragma unroll
            for (int nt = 0; nt < 4; nt++) {
                int cc = c0 + nt * 8;
                int p = (cc & 63) >> 1;
                float csA = g_cs[sA * 32 + p], snA = g_sn[sA * 32 + p];
                float csB = g_cs[sB * 32 + p], snB = g_sn[sB * 32 + p];
                float a0 = acc[mt][nt][0], a1 = acc[mt][nt][1];
                float b0 = acc[mt][nt][2], b1 = acc[mt][nt][3];
                __half* dp = dst + (size_t)rA * DD + cc;
                *(__half2*)dp = __floats2half2_rn((a0 * csA - a1 * snA) * sc,
                                                  (a0 * snA + a1 * csA) * sc);
                *(__half2*)(dp + 8 * DD) = __floats2half2_rn((b0 * csB - b1 * snB) * sc,
                                                             (b0 * snB + b1 * csB) * sc);
            }
        }
    }
}

// ---------------------------------------------------------------------------
// Output projection GEMM
// ---------------------------------------------------------------------------
__global__ __launch_bounds__(256) void gemm_out(float* __restrict__ C) {
    extern __shared__ __align__(128) char smem[];
    const uint32_t smb = smem_u32(smem);
    const int t = threadIdx.x;
    const int lane = t & 31, warp = t >> 5;
    const int qr = lane >> 2, ql = lane & 3;
    const int wm = (warp >> 2) * 64, wn = (warp & 3) * 32;
    const int bn = blockIdx.x * 128;
    const int bm = blockIdx.y * 128;

    float acc[4][4][4] = {};
    gemm_main(smb, g_oh + (size_t)bm * DD, g_wh + (size_t)3 * DD * DD + (size_t)bn * DD, acc);

    const int r0 = bm + wm + qr;
    const int c0 = bn + wn + 2 * ql;
#pragma unroll
    for (int mt = 0; mt < 4; mt++)
#pragma unroll
        for (int nt = 0; nt < 4; nt++) {
            float* cp = C + (size_t)(r0 + mt * 16) * DD + c0 + nt * 8;
            *(float2*)cp = make_float2(acc[mt][nt][0], acc[mt][nt][1]);
            *(float2*)(cp + 8 * DD) = make_float2(acc[mt][nt][2], acc[mt][nt][3]);
        }
}

// ---------------------------------------------------------------------------
// fp16 flash attention v4' (R10 base + masked-warp skip):
// no-max softmax (P = exp2(s) directly), scalar f32 ex2, q-tile 128,
// k-tile 64, P in registers, 3-stage cp.async ring, 1 barrier/k-tile,
// balanced pairing. Warps 0-3 skip the fully-masked 2nd diagonal tile.
// ---------------------------------------------------------------------------
#define HPAD 72
#define QT_B  (0)
#define KT_B(s) (128 * HPAD * 2 + (s) * (2 * 64 * HPAD * 2))
#define VT_B(s) (KT_B(s) + 64 * HPAD * 2)
#define ATTN_SMEM_B (128 * HPAD * 2 + 6 * 64 * HPAD * 2)   // 73728

__global__ __launch_bounds__(256) void attn_h() {
    extern __shared__ __align__(16) __half smh[];
    const uint32_t u0 = smem_u32(smh);
    __half* Qs = smh;

    const int h = blockIdx.y, b = blockIdx.z;
    const int t = threadIdx.x;
    const int lane = t & 31, warp = t >> 5;
    const int qr = lane >> 2, ql = lane & 3;
    const int br = lane & 7, bg = lane >> 3;

    const uint32_t offA  = ((warp * 16 + (lane & 15)) * HPAD + (lane >> 4) * 8) * 2;
    const uint32_t offBk = ((br + (bg >> 1) * 8) * HPAD + (bg & 1) * 8) * 2;
    const uint32_t offBv = ((br + (bg & 1) * 8) * HPAD + (bg >> 1) * 8) * 2;

#define AKLOAD(kt_, buf_) do {                                                      \
        const __half* kb_ = g_kh + ((size_t)b * SS + (size_t)(kt_) * 64) * DD + h * DKK; \
        const __half* vb_ = g_vh + ((size_t)b * SS + (size_t)(kt_) * 64) * DD + h * DKK; \
        uint32_t kd_ = u0 + KT_B(buf_), vd_ = u0 + VT_B(buf_);                      \
        _Pragma("unroll")                                                           \
        for (int i_ = 0; i_ < 2; i_++) {                                            \
            int idx_ = t + i_ * 256;                                                \
            int r_ = idx_ >> 3, cb_ = (idx_ & 7) * 16;                              \
            cp16(kd_ + r_ * (HPAD * 2) + cb_, kb_ + (size_t)r_ * DD + (idx_ & 7) * 8); \
            cp16(vd_ + r_ * (HPAD * 2) + cb_, vb_ + (size_t)r_ * DD + (idx_ & 7) * 8); \
        }                                                                           \
    } while (0)

#pragma unroll
    for (int pass = 0; pass < 2; pass++) {
        const int qt = pass ? blockIdx.x : 15 - blockIdx.x;   // q-tile of 128 rows
        const int nk = 2 * qt + 2;

        // load Q tile: 128 rows x 64 halves
        const __half* qb = g_qh + ((size_t)b * SS + (size_t)qt * 128) * DD + h * DKK;
#pragma unroll
        for (int i = 0; i < 4; i++) {
            int idx = t + i * 256;
            int r = idx >> 3, c = (idx & 7) * 8;
            *(uint4*)&Qs[r * HPAD + c] = *(const uint4*)&qb[(size_t)r * DD + c];
        }

        float o[8][4] = {};
        float l0 = 0.0f, l1 = 0.0f;

        AKLOAD(0, 0);
        asm volatile("cp.async.commit_group;");
        AKLOAD(1, 1);
        asm volatile("cp.async.commit_group;");

        int buf = 0;
        for (int kt = 0; kt < nk; kt++) {
            asm volatile("cp.async.wait_group 1;");
            __syncthreads();

            const uint32_t u_k = u0 + KT_B(buf);
            const uint32_t u_v = u0 + VT_B(buf);
            buf = (buf == 2) ? 0 : buf + 1;

            // warps 0-3 are fully masked on the 2nd diagonal tile -> skip.
            // (warp-uniform branch; no barriers inside; skipped contribution
            // is exactly 0: all sv masked -> ex2(-1e30) = 0)
            if (!(kt == 2 * qt + 1 && warp < 4)) {
                // ---- S = Q K^T (log2-scaled) ----
                float sv[8][4] = {};
#pragma unroll
                for (int ks = 0; ks < 4; ks++) {
                    unsigned a[4];
                    ldsm4(a, u0 + QT_B + offA + ks * 32);
#pragma unroll
                    for (int np = 0; np < 4; np++) {
                        unsigned bf[4];
                        ldsm4(bf, u_k + offBk + np * (16 * HPAD * 2) + ks * 32);
                        mma_f16(sv[2 * np],     a, &bf[0]);
                        mma_f16(sv[2 * np + 1], a, &bf[2]);
                    }
                }

                // ---- causal mask (diagonal spans k-tiles 2qt and 2qt+1) ----
                if (kt >= 2 * qt) {
                    const int off = (kt - 2 * qt) * 64;
                    const int r_lo = warp * 16 + qr - off, r_hi = r_lo + 8;
#pragma unroll
                    for (int nt = 0; nt < 8; nt++) {
                        int c0 = nt * 8 + 2 * ql, c1 = c0 + 1;
                        if (c0 > r_lo) sv[nt][0] = -1e30f;
                        if (c1 > r_lo) sv[nt][1] = -1e30f;
                        if (c0 > r_hi) sv[nt][2] = -1e30f;
                        if (c1 > r_hi) sv[nt][3] = -1e30f;
                    }
                }

                // ---- no-max softmax: P = exp2(s) ----
                float rs0 = 0.0f, rs1 = 0.0f;
#pragma unroll
                for (int nt = 0; nt < 8; nt++) {
                    sv[nt][0] = ex2(sv[nt][0]);
                    sv[nt][1] = ex2(sv[nt][1]);
                    sv[nt][2] = ex2(sv[nt][2]);
                    sv[nt][3] = ex2(sv[nt][3]);
                    rs0 += sv[nt][0] + sv[nt][1];
                    rs1 += sv[nt][2] + sv[nt][3];
                }
                l0 += rs0;
                l1 += rs1;

                // ---- P fragments directly in registers ----
                unsigned pa[4][4];
#pragma unroll
                for (int ks = 0; ks < 4; ks++) {
                    pa[ks][0] = packh2(sv[2 * ks][0],     sv[2 * ks][1]);
                    pa[ks][1] = packh2(sv[2 * ks][2],     sv[2 * ks][3]);
                    pa[ks][2] = packh2(sv[2 * ks + 1][0], sv[2 * ks + 1][1]);
                    pa[ks][3] = packh2(sv[2 * ks + 1][2], sv[2 * ks + 1][3]);
                }

                // ---- O += P V  (V row-major via ldmatrix.trans) ----
#pragma unroll
                for (int ks = 0; ks < 4; ks++) {
#pragma unroll
                    for (int np = 0; np < 4; np++) {
                        unsigned bf[4];
                        ldsm4t(bf, u_v + offBv + ks * (16 * HPAD * 2) + np * 32);
                        mma_f16(o[2 * np],     pa[ks], &bf[0]);
                        mma_f16(o[2 * np + 1], pa[ks], &bf[2]);
                    }
                }
            }

            // prefetch k-tile kt+2 into ring slot
            if (kt + 2 < nk) AKLOAD(kt + 2, (kt + 2) % 3);
            asm volatile("cp.async.commit_group;");
        }

        // ---- row-sum reduce across quad lanes, then epilogue ----
        l0 += __shfl_xor_sync(0xffffffffu, l0, 1);
        l0 += __shfl_xor_sync(0xffffffffu, l0, 2);
        l1 += __shfl_xor_sync(0xffffffffu, l1, 1);
        l1 += __shfl_xor_sync(0xffffffffu, l1, 2);

        const float inv0 = 1.0f / l0, inv1 = 1.0f / l1;
        __half* ob = g_oh + ((size_t)b * SS + (size_t)qt * 128 + warp * 16 + qr) * DD + h * DKK;
#pragma unroll
        for (int nt = 0; nt < 8; nt++) {
            int c0 = nt * 8 + 2 * ql;
            *(__half2*)&ob[c0] = __floats2half2_rn(o[nt][0] * inv0, o[nt][1] * inv0);
            *(__half2*)&ob[(size_t)8 * DD + c0] = __floats2half2_rn(o[nt][2] * inv1, o[nt][3] * inv1);
        }
        __syncthreads();
    }
#undef AKLOAD
}

// ---------------------------------------------------------------------------
extern "C" void kernel_launch(void* const* d_in, const int* in_sizes, int n_in,
                              void* d_out, int out_size) {
    const float* x  = (const float*)d_in[0];
    const float* wq = (const float*)d_in[1];
    const float* wk = (const float*)d_in[2];
    const float* wv = (const float*)d_in[3];
    const float* wo = (const float*)d_in[4];
    const int*   tp = (const int*)d_in[5];
    float* out = (float*)d_out;

    rope_table<<<(SS * 32) / 256, 256>>>(tp);
    conv_all<<<(NX4 + 4 * NW4) / 256, 256>>>(x, wq, wk, wv, wo);

    const int GEMM_SMEM = 4 * GSTG;          // 81920 B
    cudaFuncSetAttribute(gemm_qkv, cudaFuncAttributeMaxDynamicSharedMemorySize, GEMM_SMEM);
    cudaFuncSetAttribute(gemm_out, cudaFuncAttributeMaxDynamicSharedMemorySize, GEMM_SMEM);

    gemm_qkv<<<dim3(24, (BB * SS) / 128), 256, GEMM_SMEM>>>();

    cudaFuncSetAttribute(attn_h, cudaFuncAttributeMaxDynamicSharedMemorySize, ATTN_SMEM_B);
    attn_h<<<dim3(SS / 256, HH, BB), 256, ATTN_SMEM_B>>>();

    gemm_out<<<dim3(DD / 128, (BB * SS) / 128), 256, GEMM_SMEM>>>(out);
}

// round 13
// speedup vs baseline: 1.4991x; 1.0610x over previous
#include <cuda_runtime.h>
#include <cuda_fp16.h>
#include <math.h>
#include <stdint.h>

#define BB 4
#define SS 2048
#define DD 1024
#define HH 16
#define DKK 64
#define NTOT (BB*SS*DD)

// ---------------------------------------------------------------------------
// Scratch (device globals — no allocations allowed)
// ---------------------------------------------------------------------------
__device__ float  g_cs[SS * 32];
__device__ float  g_sn[SS * 32];
__device__ __half g_xh[NTOT];
__device__ __half g_wh[4 * DD * DD];
__device__ __half g_qh[NTOT];
__device__ __half g_kh[NTOT];
__device__ __half g_vh[NTOT];
__device__ __half g_oh[NTOT];

// ---------------------------------------------------------------------------
// mma / ldmatrix / cp.async helpers
// ---------------------------------------------------------------------------
__device__ __forceinline__ void mma_f16(float* c, const unsigned* a, const unsigned* b) {
    asm volatile(
        "mma.sync.aligned.m16n8k16.row.col.f32.f16.f16.f32 "
        "{%0,%1,%2,%3},{%4,%5,%6,%7},{%8,%9},{%0,%1,%2,%3};\n"
        : "+f"(c[0]), "+f"(c[1]), "+f"(c[2]), "+f"(c[3])
        : "r"(a[0]), "r"(a[1]), "r"(a[2]), "r"(a[3]), "r"(b[0]), "r"(b[1]));
}
__device__ __forceinline__ void ldsm4(unsigned* r, uint32_t addr) {
    asm volatile("ldmatrix.sync.aligned.m8n8.x4.shared.b16 {%0,%1,%2,%3}, [%4];"
        : "=r"(r[0]), "=r"(r[1]), "=r"(r[2]), "=r"(r[3]) : "r"(addr));
}
__device__ __forceinline__ void ldsm4t(unsigned* r, uint32_t addr) {
    asm volatile("ldmatrix.sync.aligned.m8n8.x4.trans.shared.b16 {%0,%1,%2,%3}, [%4];"
        : "=r"(r[0]), "=r"(r[1]), "=r"(r[2]), "=r"(r[3]) : "r"(addr));
}
__device__ __forceinline__ void cp16(uint32_t dst, const void* src) {
    asm volatile("cp.async.cg.shared.global [%0], [%1], 16;" :: "r"(dst), "l"(src));
}
__device__ __forceinline__ uint32_t smem_u32(const void* p) {
    uint32_t a;
    asm("{ .reg .u64 t; cvta.to.shared.u64 t, %1; cvt.u32.u64 %0, t; }" : "=r"(a) : "l"(p));
    return a;
}
__device__ __forceinline__ unsigned packh2(float a, float b) {
    __half2 h = __floats2half2_rn(a, b);
    return *(unsigned*)&h;
}
__device__ __forceinline__ float ex2(float x) {
    float y;
    asm("ex2.approx.f32 %0, %1;" : "=f"(y) : "f"(x));
    return y;
}

// ---------------------------------------------------------------------------
// RoPE table (fp64-exact inv_freq)
// ---------------------------------------------------------------------------
__global__ void rope_table(const int* __restrict__ tp) {
    int i = blockIdx.x * blockDim.x + threadIdx.x;
    int s = i >> 5, p = i & 31;
    float pos = (float)tp[s];
    float inv = (float)exp(-(double)p * 0.28782313662425572);
    float ang = pos * inv;
    float sn, cs;
    sincosf(ang, &sn, &cs);
    g_cs[i] = cs;
    g_sn[i] = sn;
}

// ---------------------------------------------------------------------------
// One-shot fp32 -> fp16 conversion: x + 4 weights
// ---------------------------------------------------------------------------
#define NX4 (NTOT/4)
#define NW4 ((DD*DD)/4)
__global__ void conv_all(const float* __restrict__ x,  const float* __restrict__ wq,
                         const float* __restrict__ wk, const float* __restrict__ wv,
                         const float* __restrict__ wo) {
    int i = blockIdx.x * blockDim.x + threadIdx.x;
    const float* src;
    __half* dst;
    int j;
    if (i < NX4) { src = x; dst = g_xh; j = i; }
    else {
        int r = i - NX4;
        int seg = r / NW4;
        j = r - seg * NW4;
        src = (seg == 0) ? wq : (seg == 1) ? wk : (seg == 2) ? wv : wo;
        dst = g_wh + (size_t)seg * DD * DD;
    }
    float4 v = ((const float4*)src)[j];
    ((__half2*)dst)[2 * j]     = __floats2half2_rn(v.x, v.y);
    ((__half2*)dst)[2 * j + 1] = __floats2half2_rn(v.z, v.w);
}

// ---------------------------------------------------------------------------
// GEMM mainloop: single barrier per k-stage.
// ---------------------------------------------------------------------------
#define GSTG 20480
__device__ __forceinline__ void gemm_main(uint32_t smb, const __half* Ag,
                                          const __half* Bg, float acc[4][4][4]) {
    const int t = threadIdx.x;
    const int lane = t & 31, warp = t >> 5;
    const int wm = (warp >> 2) * 64, wn = (warp & 3) * 32;
    const int chunk = t & 3, row0 = t >> 2;
    Ag += chunk * 8;
    Bg += chunk * 8;

    const uint32_t a_off = ((wm + (lane & 15)) * 40 + (lane >> 4) * 8) * 2;
    const int br = lane & 7, bg = lane >> 3;
    const uint32_t b_off = ((wn + br + (bg >> 1) * 8) * 40 + (bg & 1) * 8) * 2;

#pragma unroll
    for (int ps = 0; ps < 3; ps++) {
        uint32_t sb = smb + ps * GSTG;
        const __half* ga = Ag + ps * 32;
        const __half* gb = Bg + ps * 32;
#pragma unroll
        for (int j = 0; j < 2; j++) {
            int row = row0 + j * 64;
            cp16(sb + row * 80 + chunk * 16, ga + (size_t)row * DD);
            cp16(sb + 128 * 80 + row * 80 + chunk * 16, gb + (size_t)row * DD);
        }
        asm volatile("cp.async.commit_group;");
    }

    for (int s = 0; s < 32; s++) {
        asm volatile("cp.async.wait_group 2;");
        __syncthreads();
        const uint32_t sA = smb + (s & 3) * GSTG;
        const uint32_t sB = sA + 128 * 80;
#pragma unroll
        for (int ks = 0; ks < 2; ks++) {
            unsigned af[4][4], bf[2][4];
#pragma unroll
            for (int mt = 0; mt < 4; mt++)
                ldsm4(af[mt], sA + a_off + mt * (16 * 80) + ks * 32);
#pragma unroll
            for (int np = 0; np < 2; np++)
                ldsm4(bf[np], sB + b_off + np * (16 * 80) + ks * 32);
#pragma unroll
            for (int mt = 0; mt < 4; mt++)
#pragma unroll
                for (int nt = 0; nt < 4; nt++)
                    mma_f16(acc[mt][nt], af[mt], &bf[nt >> 1][(nt & 1) * 2]);
        }
        if (s + 3 < 32) {
            uint32_t sb = smb + ((s + 3) & 3) * GSTG;
            const __half* ga = Ag + (s + 3) * 32;
            const __half* gb = Bg + (s + 3) * 32;
#pragma unroll
            for (int j = 0; j < 2; j++) {
                int row = row0 + j * 64;
                cp16(sb + row * 80 + chunk * 16, ga + (size_t)row * DD);
                cp16(sb + 128 * 80 + row * 80 + chunk * 16, gb + (size_t)row * DD);
            }
        }
        asm volatile("cp.async.commit_group;");
    }
}

// ---------------------------------------------------------------------------
// Fused QKV GEMM + RoPE epilogue. Q scale 0.125*log2(e) (exp2 softmax).
// ---------------------------------------------------------------------------
#define QSCALE 0.1803368801111204f   // 0.125 * log2(e)
__global__ __launch_bounds__(256) void gemm_qkv() {
    extern __shared__ __align__(128) char smem[];
    const uint32_t smb = smem_u32(smem);
    const int t = threadIdx.x;
    const int lane = t & 31, warp = t >> 5;
    const int qr = lane >> 2, ql = lane & 3;
    const int wm = (warp >> 2) * 64, wn = (warp & 3) * 32;
    const int w  = blockIdx.x >> 3;
    const int bn = (blockIdx.x & 7) * 128;
    const int bm = blockIdx.y * 128;

    float acc[4][4][4] = {};
    gemm_main(smb, g_xh + (size_t)bm * DD, g_wh + (size_t)w * DD * DD + (size_t)bn * DD, acc);

    const int r0 = bm + wm + qr;
    const int c0 = bn + wn + 2 * ql;
    if (w == 2) {
#pragma unroll
        for (int mt = 0; mt < 4; mt++)
#pragma unroll
            for (int nt = 0; nt < 4; nt++) {
                __half* vp = g_vh + (size_t)(r0 + mt * 16) * DD + c0 + nt * 8;
                *(__half2*)vp = __floats2half2_rn(acc[mt][nt][0], acc[mt][nt][1]);
                *(__half2*)(vp + 8 * DD) = __floats2half2_rn(acc[mt][nt][2], acc[mt][nt][3]);
            }
    } else {
        __half* dst = (w == 0) ? g_qh : g_kh;
        const float sc = (w == 0) ? QSCALE : 1.0f;
#pragma unroll
        for (int mt = 0; mt < 4; mt++) {
            int rA = r0 + mt * 16;
            int rB = rA + 8;
            int sA = rA & (SS - 1), sB = rB & (SS - 1);
#pragma unroll
            for (int nt = 0; nt < 4; nt++) {
                int cc = c0 + nt * 8;
                int p = (cc & 63) >> 1;
                float csA = g_cs[sA * 32 + p], snA = g_sn[sA * 32 + p];
                float csB = g_cs[sB * 32 + p], snB = g_sn[sB * 32 + p];
                float a0 = acc[mt][nt][0], a1 = acc[mt][nt][1];
                float b0 = acc[mt][nt][2], b1 = acc[mt][nt][3];
                __half* dp = dst + (size_t)rA * DD + cc;
                *(__half2*)dp = __floats2half2_rn((a0 * csA - a1 * snA) * sc,
                                                  (a0 * snA + a1 * csA) * sc);
                *(__half2*)(dp + 8 * DD) = __floats2half2_rn((b0 * csB - b1 * snB) * sc,
                                                             (b0 * snB + b1 * csB) * sc);
            }
        }
    }
}

// ---------------------------------------------------------------------------
// Output projection GEMM
// ---------------------------------------------------------------------------
__global__ __launch_bounds__(256) void gemm_out(float* __restrict__ C) {
    extern __shared__ __align__(128) char smem[];
    const uint32_t smb = smem_u32(smem);
    const int t = threadIdx.x;
    const int lane = t & 31, warp = t >> 5;
    const int qr = lane >> 2, ql = lane & 3;
    const int wm = (warp >> 2) * 64, wn = (warp & 3) * 32;
    const int bn = blockIdx.x * 128;
    const int bm = blockIdx.y * 128;

    float acc[4][4][4] = {};
    gemm_main(smb, g_oh + (size_t)bm * DD, g_wh + (size_t)3 * DD * DD + (size_t)bn * DD, acc);

    const int r0 = bm + wm + qr;
    const int c0 = bn + wn + 2 * ql;
#pragma unroll
    for (int mt = 0; mt < 4; mt++)
#pragma unroll
        for (int nt = 0; nt < 4; nt++) {
            float* cp = C + (size_t)(r0 + mt * 16) * DD + c0 + nt * 8;
            *(float2*)cp = make_float2(acc[mt][nt][0], acc[mt][nt][1]);
            *(float2*)(cp + 8 * DD) = make_float2(acc[mt][nt][2], acc[mt][nt][3]);
        }
}

// ---------------------------------------------------------------------------
// fp16 flash attention v6 = R10 inner loop, single q-tile per block,
// largest-first dispatch (qt = 15 - bx) for LPT-style wave balancing.
// no-max softmax (P = exp2(s)), q-tile 128, k-tile 64, P in registers,
// 3-stage cp.async ring, 1 barrier per k-tile.
// ---------------------------------------------------------------------------
#define HPAD 72
#define QT_B  (0)
#define KT_B(s) (128 * HPAD * 2 + (s) * (2 * 64 * HPAD * 2))
#define VT_B(s) (KT_B(s) + 64 * HPAD * 2)
#define ATTN_SMEM_B (128 * HPAD * 2 + 6 * 64 * HPAD * 2)   // 73728

__global__ __launch_bounds__(256) void attn_h() {
    extern __shared__ __align__(16) __half smh[];
    const uint32_t u0 = smem_u32(smh);
    __half* Qs = smh;

    const int h = blockIdx.y, b = blockIdx.z;
    const int t = threadIdx.x;
    const int lane = t & 31, warp = t >> 5;
    const int qr = lane >> 2, ql = lane & 3;
    const int br = lane & 7, bg = lane >> 3;

    const uint32_t offA  = ((warp * 16 + (lane & 15)) * HPAD + (lane >> 4) * 8) * 2;
    const uint32_t offBk = ((br + (bg >> 1) * 8) * HPAD + (bg & 1) * 8) * 2;
    const uint32_t offBv = ((br + (bg & 1) * 8) * HPAD + (bg >> 1) * 8) * 2;

#define AKLOAD(kt_, buf_) do {                                                      \
        const __half* kb_ = g_kh + ((size_t)b * SS + (size_t)(kt_) * 64) * DD + h * DKK; \
        const __half* vb_ = g_vh + ((size_t)b * SS + (size_t)(kt_) * 64) * DD + h * DKK; \
        uint32_t kd_ = u0 + KT_B(buf_), vd_ = u0 + VT_B(buf_);                      \
        _Pragma("unroll")                                                           \
        for (int i_ = 0; i_ < 2; i_++) {                                            \
            int idx_ = t + i_ * 256;                                                \
            int r_ = idx_ >> 3, cb_ = (idx_ & 7) * 16;                              \
            cp16(kd_ + r_ * (HPAD * 2) + cb_, kb_ + (size_t)r_ * DD + (idx_ & 7) * 8); \
            cp16(vd_ + r_ * (HPAD * 2) + cb_, vb_ + (size_t)r_ * DD + (idx_ & 7) * 8); \
        }                                                                           \
    } while (0)

    const int qt = 15 - (int)blockIdx.x;   // largest q-tile first (LPT dispatch)
    const int nk = 2 * qt + 2;

    // load Q tile: 128 rows x 64 halves
    const __half* qb = g_qh + ((size_t)b * SS + (size_t)qt * 128) * DD + h * DKK;
#pragma unroll
    for (int i = 0; i < 4; i++) {
        int idx = t + i * 256;
        int r = idx >> 3, c = (idx & 7) * 8;
        *(uint4*)&Qs[r * HPAD + c] = *(const uint4*)&qb[(size_t)r * DD + c];
    }

    float o[8][4] = {};
    float l0 = 0.0f, l1 = 0.0f;

    AKLOAD(0, 0);
    asm volatile("cp.async.commit_group;");
    AKLOAD(1, 1);
    asm volatile("cp.async.commit_group;");

    int buf = 0;
    for (int kt = 0; kt < nk; kt++) {
        asm volatile("cp.async.wait_group 1;");
        __syncthreads();

        const uint32_t u_k = u0 + KT_B(buf);
        const uint32_t u_v = u0 + VT_B(buf);
        buf = (buf == 2) ? 0 : buf + 1;

        // ---- S = Q K^T (log2-scaled) ----
        float sv[8][4] = {};
#pragma unroll
        for (int ks = 0; ks < 4; ks++) {
            unsigned a[4];
            ldsm4(a, u0 + QT_B + offA + ks * 32);
#pragma unroll
            for (int np = 0; np < 4; np++) {
                unsigned bf[4];
                ldsm4(bf, u_k + offBk + np * (16 * HPAD * 2) + ks * 32);
                mma_f16(sv[2 * np],     a, &bf[0]);
                mma_f16(sv[2 * np + 1], a, &bf[2]);
            }
        }

        // ---- causal mask (diagonal spans k-tiles 2qt and 2qt+1) ----
        if (kt >= 2 * qt) {
            const int off = (kt - 2 * qt) * 64;
            const int r_lo = warp * 16 + qr - off, r_hi = r_lo + 8;
#pragma unroll
            for (int nt = 0; nt < 8; nt++) {
                int c0 = nt * 8 + 2 * ql, c1 = c0 + 1;
                if (c0 > r_lo) sv[nt][0] = -1e30f;
                if (c1 > r_lo) sv[nt][1] = -1e30f;
                if (c0 > r_hi) sv[nt][2] = -1e30f;
                if (c1 > r_hi) sv[nt][3] = -1e30f;
            }
        }

        // ---- no-max softmax: P = exp2(s) ----
        float rs0 = 0.0f, rs1 = 0.0f;
#pragma unroll
        for (int nt = 0; nt < 8; nt++) {
            sv[nt][0] = ex2(sv[nt][0]);
            sv[nt][1] = ex2(sv[nt][1]);
            sv[nt][2] = ex2(sv[nt][2]);
            sv[nt][3] = ex2(sv[nt][3]);
            rs0 += sv[nt][0] + sv[nt][1];
            rs1 += sv[nt][2] + sv[nt][3];
        }
        l0 += rs0;
        l1 += rs1;

        // ---- P fragments directly in registers (C-layout == A-layout) ----
        unsigned pa[4][4];
#pragma unroll
        for (int ks = 0; ks < 4; ks++) {
            pa[ks][0] = packh2(sv[2 * ks][0],     sv[2 * ks][1]);
            pa[ks][1] = packh2(sv[2 * ks][2],     sv[2 * ks][3]);
            pa[ks][2] = packh2(sv[2 * ks + 1][0], sv[2 * ks + 1][1]);
            pa[ks][3] = packh2(sv[2 * ks + 1][2], sv[2 * ks + 1][3]);
        }

        // ---- O += P V  (V row-major via ldmatrix.trans) ----
#pragma unroll
        for (int ks = 0; ks < 4; ks++) {
#pragma unroll
            for (int np = 0; np < 4; np++) {
                unsigned bf[4];
                ldsm4t(bf, u_v + offBv + ks * (16 * HPAD * 2) + np * 32);
                mma_f16(o[2 * np],     pa[ks], &bf[0]);
                mma_f16(o[2 * np + 1], pa[ks], &bf[2]);
            }
        }

        // prefetch k-tile kt+2 into ring slot
        if (kt + 2 < nk) AKLOAD(kt + 2, (kt + 2) % 3);
        asm volatile("cp.async.commit_group;");
    }

    // ---- row-sum reduce across quad lanes, then epilogue ----
    l0 += __shfl_xor_sync(0xffffffffu, l0, 1);
    l0 += __shfl_xor_sync(0xffffffffu, l0, 2);
    l1 += __shfl_xor_sync(0xffffffffu, l1, 1);
    l1 += __shfl_xor_sync(0xffffffffu, l1, 2);

    const float inv0 = 1.0f / l0, inv1 = 1.0f / l1;
    __half* ob = g_oh + ((size_t)b * SS + (size_t)qt * 128 + warp * 16 + qr) * DD + h * DKK;
#pragma unroll
    for (int nt = 0; nt < 8; nt++) {
        int c0 = nt * 8 + 2 * ql;
        *(__half2*)&ob[c0] = __floats2half2_rn(o[nt][0] * inv0, o[nt][1] * inv0);
        *(__half2*)&ob[(size_t)8 * DD + c0] = __floats2half2_rn(o[nt][2] * inv1, o[nt][3] * inv1);
    }
#undef AKLOAD
}

// ---------------------------------------------------------------------------
extern "C" void kernel_launch(void* const* d_in, const int* in_sizes, int n_in,
                              void* d_out, int out_size) {
    const float* x  = (const float*)d_in[0];
    const float* wq = (const float*)d_in[1];
    const float* wk = (const float*)d_in[2];
    const float* wv = (const float*)d_in[3];
    const float* wo = (const float*)d_in[4];
    const int*   tp = (const int*)d_in[5];
    float* out = (float*)d_out;

    rope_table<<<(SS * 32) / 256, 256>>>(tp);
    conv_all<<<(NX4 + 4 * NW4) / 256, 256>>>(x, wq, wk, wv, wo);

    const int GEMM_SMEM = 4 * GSTG;          // 81920 B
    cudaFuncSetAttribute(gemm_qkv, cudaFuncAttributeMaxDynamicSharedMemorySize, GEMM_SMEM);
    cudaFuncSetAttribute(gemm_out, cudaFuncAttributeMaxDynamicSharedMemorySize, GEMM_SMEM);

    gemm_qkv<<<dim3(24, (BB * SS) / 128), 256, GEMM_SMEM>>>();

    cudaFuncSetAttribute(attn_h, cudaFuncAttributeMaxDynamicSharedMemorySize, ATTN_SMEM_B);
    attn_h<<<dim3(16, HH, BB), 256, ATTN_SMEM_B>>>();

    gemm_out<<<dim3(DD / 128, (BB * SS) / 128), 256, GEMM_SMEM>>>(out);
}